// round 7
// baseline (speedup 1.0000x reference)
#include <cuda_runtime.h>

// DMTSkeletonize: exact squared-EDT with adaptive candidate window (bit-exact:
// excluding j with (i-j)^2 >= running-min can't change the min since f >= 0;
// all finite arithmetic < 2^24 so every kept term is exact), plus a z-marching
// fused 3x3x3 local-max skeleton kernel on d^2.
//
// Shapes: img [4,1,160,160,160] fp32. B=4, D=H=W=160.

#define WW    160
#define HWSZ  25600      // H*W
#define DHWSZ 4096000    // D*H*W
#define NTOT  16384000   // B*D*H*W
#define FINF  1e12f
#define NEGINF (-3.0e38f)

// Scratch (device globals — no allocation anywhere, per harness rules)
__device__ float g_A[NTOT];
__device__ float g_B[NTOT];

// ---------------------------------------------------------------------------
// EDT 1D pass: out[line][i] = min_j fl(f[line][j] + (i-j)^2)
// MODE 0: lines along x (contiguous); input = img binarized; writes g_A
// MODE 1: lines along y (stride W);   g_A -> g_B
// MODE 2: lines along z (stride H*W); g_B -> g_A
// 512 threads, 32 lines/block; thread = (line, segment-of-10); adaptive
// outward scan, FIVE adjacent outputs in flight per thread (ILP=5).
// ---------------------------------------------------------------------------
template <int MODE>
__global__ __launch_bounds__(512) void edt_pass_kernel(const float* __restrict__ img)
{
    __shared__ float fsh[32][161];  // pad: conflict-free transposed access

    const float* __restrict__ in  = (MODE == 0) ? img : (MODE == 1 ? g_A : g_B);
    float* __restrict__       out = (MODE == 1) ? g_B : g_A;

    const int tid = threadIdx.x;
    const int bid = blockIdx.x;

    long base;
    int stride;
    if (MODE == 0) {
        base = (long)bid * (32 * 160);
        stride = 1;
    } else if (MODE == 1) {
        int p  = bid / 5;            // p = b*160 + z
        int x0 = (bid % 5) * 32;
        base = (long)p * HWSZ + x0;
        stride = WW;
    } else {
        int p  = bid / 5;            // p = b*160 + y
        int x0 = (bid % 5) * 32;
        int b = p / 160, y = p - b * 160;
        base = (long)b * DHWSZ + (long)y * WW + x0;
        stride = HWSZ;
    }

    // ---- load tile into shared (coalesced) ----
    if (MODE == 0) {
        for (int idx = tid; idx < 32 * 160; idx += 512) {
            int l = idx / 160;
            int j = idx - l * 160;
            float v = in[base + idx];
            fsh[l][j] = (v > 0.5f) ? 0.0f : FINF;     // binarize + invert
        }
    } else {
        for (int idx = tid; idx < 32 * 160; idx += 512) {
            int j = idx >> 5;
            int l = idx & 31;
            fsh[l][j] = in[base + (long)j * stride + l];
        }
    }
    __syncthreads();

    // ---- adaptive-window min-plus transform, 5 chains in flight ----
    const int l = tid >> 4;          // line 0..31
    const int s = tid & 15;          // segment 0..15 (10 outputs each)
    const float* __restrict__ f = fsh[l];

    float res[10];
#pragma unroll 1
    for (int h = 0; h < 2; h++) {
        const int i0 = s * 10 + h * 5;   // 5 adjacent outputs i0..i0+4
        float a0 = f[i0 + 0];            // j = i term: exact
        float a1 = f[i0 + 1];
        float a2 = f[i0 + 2];
        float a3 = f[i0 + 3];
        float a4 = f[i0 + 4];
#pragma unroll 1
        for (int k = 1; k < 160; k++) {
            const float kk = (float)(k * k);        // exact in fp32
            const bool g0 = kk < a0, g1 = kk < a1, g2 = kk < a2,
                       g3 = kk < a3, g4 = kk < a4;
            if (!(g0 | g1 | g2 | g3 | g4)) break;
            const int jn = i0 - k, jp = i0 + k;
            if (g0) {
                if (jn + 0 >= 0)   a0 = fminf(a0, kk + f[jn + 0]);
                if (jp + 0 < 160)  a0 = fminf(a0, kk + f[jp + 0]);
            }
            if (g1) {
                if (jn + 1 >= 0)   a1 = fminf(a1, kk + f[jn + 1]);
                if (jp + 1 < 160)  a1 = fminf(a1, kk + f[jp + 1]);
            }
            if (g2) {
                if (jn + 2 >= 0)   a2 = fminf(a2, kk + f[jn + 2]);
                if (jp + 2 < 160)  a2 = fminf(a2, kk + f[jp + 2]);
            }
            if (g3) {
                if (jn + 3 >= 0)   a3 = fminf(a3, kk + f[jn + 3]);
                if (jp + 3 < 160)  a3 = fminf(a3, kk + f[jp + 3]);
            }
            if (g4) {
                if (jn + 4 >= 0)   a4 = fminf(a4, kk + f[jn + 4]);
                if (jp + 4 < 160)  a4 = fminf(a4, kk + f[jp + 4]);
            }
        }
        res[h * 5 + 0] = a0;
        res[h * 5 + 1] = a1;
        res[h * 5 + 2] = a2;
        res[h * 5 + 3] = a3;
        res[h * 5 + 4] = a4;
    }

    __syncthreads();   // all reads of fsh done before overwrite
#pragma unroll
    for (int o = 0; o < 10; o++) fsh[l][s * 10 + o] = res[o];
    __syncthreads();

    // ---- coalesced store ----
    if (MODE == 0) {
        for (int idx = tid; idx < 32 * 160; idx += 512) {
            int ll = idx / 160;
            int j  = idx - ll * 160;
            out[base + idx] = fsh[ll][j];
        }
    } else {
        for (int idx = tid; idx < 32 * 160; idx += 512) {
            int j  = idx >> 5;
            int ll = idx & 31;
            out[base + (long)j * stride + ll] = fsh[ll][j];
        }
    }
}

// ---------------------------------------------------------------------------
// Fused 3x3x3 neighborhood max + skeleton + multiply, z-marching version.
// Block: 256 threads = (x=32, y=8), tile 32x32 in xy (each thread 4 y-strips),
// marches a 10-slice z-chunk with double-buffered 34x34 halo slices in shared.
// grid = (5, 5, 64): xy tiles x (batch*16 + zchunk). 1600 blocks, ~8/SM.
// ---------------------------------------------------------------------------
__global__ __launch_bounds__(256) void skel_kernel(const float* __restrict__ img,
                                                   float* __restrict__ out)
{
    __shared__ float sA[2][34][36];   // pad 36: conflict-free rows

    const int tid = threadIdx.x;
    const int tx  = tid & 31;
    const int ty  = tid >> 5;                // 0..7
    const int x0  = blockIdx.x * 32;
    const int y0  = blockIdx.y * 32;
    const int b   = blockIdx.z >> 4;         // 0..3
    const int z0  = (blockIdx.z & 15) * 10;  // 0..150
    const long gbase = (long)b * DHWSZ;
    const float* __restrict__ A = g_A + gbase;

    float xa[4], xb[4];       // xy-max at slice zs-2, zs-1
    float ch[4];              // center value at slice zs-1
#pragma unroll
    for (int s_ = 0; s_ < 4; s_++) { xa[s_] = NEGINF; xb[s_] = NEGINF; ch[s_] = 0.0f; }

    // march slices zs = z0-1 .. z0+10
#pragma unroll 1
    for (int it = 0; it < 12; it++) {
        const int zs = z0 - 1 + it;
        const int buf = it & 1;

        // load slice zs (34x34 halo, OOB = -inf)
        const bool zok = (zs >= 0) & (zs < 160);
        const float* __restrict__ S = A + (long)zs * HWSZ;
        for (int idx = tid; idx < 34 * 34; idx += 256) {
            int hy = idx / 34;
            int hx = idx - hy * 34;
            int gx = x0 + hx - 1, gy = y0 + hy - 1;
            float v = NEGINF;
            if (zok && gx >= 0 && gx < 160 && gy >= 0 && gy < 160)
                v = S[gy * WW + gx];
            sA[buf][hy][hx] = v;
        }
        __syncthreads();

        // compute 3x3 xy-max + center for this slice, emit output for zs-1
#pragma unroll
        for (int s_ = 0; s_ < 4; s_++) {
            const int hy = ty + 8 * s_ + 1;
            float m0 = fmaxf(fmaxf(sA[buf][hy - 1][tx], sA[buf][hy - 1][tx + 1]), sA[buf][hy - 1][tx + 2]);
            float c  = sA[buf][hy][tx + 1];
            float m1 = fmaxf(fmaxf(sA[buf][hy][tx], c), sA[buf][hy][tx + 2]);
            float m2 = fmaxf(fmaxf(sA[buf][hy + 1][tx], sA[buf][hy + 1][tx + 1]), sA[buf][hy + 1][tx + 2]);
            float xn = fmaxf(fmaxf(m0, m1), m2);

            if (it >= 2) {      // output at zo = zs-1 in [z0, z0+10)
                float m = fmaxf(fmaxf(xa[s_], xb[s_]), xn);
                float cc = ch[s_];
                long gi = gbase + (long)(zs - 1) * HWSZ + (y0 + ty + 8 * s_) * WW + (x0 + tx);
                out[gi] = (cc >= m && cc > 0.0f) ? img[gi] : 0.0f;
            }
            xa[s_] = xb[s_];
            xb[s_] = xn;
            ch[s_] = c;
        }
        // single barrier per slice is safe: a thread's write of buf at it+2
        // is ordered after sync#(it+1), which follows ALL threads' reads at it.
    }
}

// ---------------------------------------------------------------------------
extern "C" void kernel_launch(void* const* d_in, const int* in_sizes, int n_in,
                              void* d_out, int out_size)
{
    const float* img = (const float*)d_in[0];
    float* out = (float*)d_out;

    // EDT: x -> y -> z  (g_A holds final d^2)
    edt_pass_kernel<0><<<3200, 512>>>(img);
    edt_pass_kernel<1><<<3200, 512>>>(nullptr);
    edt_pass_kernel<2><<<3200, 512>>>(nullptr);

    // Fused 3x3x3 max + skeleton + multiply (z-marching, 10-slice chunks)
    skel_kernel<<<dim3(5, 5, 64), 256>>>(img, out);
}

// round 8
// speedup vs baseline: 1.0907x; 1.0907x over previous
#include <cuda_runtime.h>

// DMTSkeletonize: exact squared-EDT with adaptive candidate window (bit-exact:
// excluding j with (i-j)^2 >= running-min can't change the min since f >= 0;
// all finite values < 2^24 so kept terms are exactly the reference's), plus a
// software-pipelined z-marching 3x3x3 local-max skeleton on d^2.
//
// Shapes: img [4,1,160,160,160] fp32. B=4, D=H=W=160.

#define WW    160
#define HWSZ  25600      // H*W
#define DHWSZ 4096000    // D*H*W
#define NTOT  16384000   // B*D*H*W
#define FINF  1e12f
#define NEGINF (-3.0e38f)

// Scratch (device globals — no allocation anywhere, per harness rules)
__device__ float g_A[NTOT];
__device__ float g_B[NTOT];

// ---------------------------------------------------------------------------
// EDT 1D pass: out[line][i] = min_j fl(f[line][j] + (i-j)^2)
// MODE 0: x lines (contiguous), input = img binarized -> g_A
// MODE 1: y lines (stride W),   g_A -> g_B
// MODE 2: z lines (stride H*W), g_B -> g_A
// 512 threads, 32 lines/block; thread = (line, segment-of-10); adaptive
// outward scan, TWO ADJACENT outputs in flight (ILP=2, correlated windows).
// ---------------------------------------------------------------------------
template <int MODE>
__global__ __launch_bounds__(512) void edt_pass_kernel(const float* __restrict__ img)
{
    __shared__ float fsh[32][161];  // pad: conflict-free transposed access

    const float* __restrict__ in  = (MODE == 0) ? img : (MODE == 1 ? g_A : g_B);
    float* __restrict__       out = (MODE == 1) ? g_B : g_A;

    const int tid = threadIdx.x;
    const int bid = blockIdx.x;

    long base;
    int stride;
    if (MODE == 0) {
        base = (long)bid * (32 * 160);
        stride = 1;
    } else if (MODE == 1) {
        int p  = bid / 5;            // p = b*160 + z
        int x0 = (bid % 5) * 32;
        base = (long)p * HWSZ + x0;
        stride = WW;
    } else {
        int p  = bid / 5;            // p = b*160 + y
        int x0 = (bid % 5) * 32;
        int b = p / 160, y = p - b * 160;
        base = (long)b * DHWSZ + (long)y * WW + x0;
        stride = HWSZ;
    }

    // ---- load tile into shared (coalesced) ----
    if (MODE == 0) {
        for (int idx = tid; idx < 32 * 160; idx += 512) {
            int l = idx / 160;
            int j = idx - l * 160;
            float v = in[base + idx];
            fsh[l][j] = (v > 0.5f) ? 0.0f : FINF;     // binarize + invert
        }
    } else {
        for (int idx = tid; idx < 32 * 160; idx += 512) {
            int j = idx >> 5;
            int l = idx & 31;
            fsh[l][j] = in[base + (long)j * stride + l];
        }
    }
    __syncthreads();

    // ---- adaptive-window min-plus transform, 2 adjacent chains in flight ----
    const int l = tid >> 4;          // line 0..31
    const int s = tid & 15;          // segment 0..15 (10 outputs each)
    const float* __restrict__ f = fsh[l];

    float res[10];
#pragma unroll 1
    for (int o = 0; o < 5; o++) {
        const int i1 = s * 10 + 2 * o;     // adjacent pair (i1, i1+1)
        const int i2 = i1 + 1;
        float a1 = f[i1];            // j = i term: exact
        float a2 = f[i2];
#pragma unroll 1
        for (int k = 1; k < 160; k++) {
            const float kk = (float)(k * k);        // exact in fp32
            const bool g1 = kk < a1;
            const bool g2 = kk < a2;
            if (!(g1 | g2)) break;
            if (g1) {
                int jn = i1 - k, jp = i1 + k;
                if (jn >= 0)  a1 = fminf(a1, kk + f[jn]);  // 1 rounding = ref
                if (jp < 160) a1 = fminf(a1, kk + f[jp]);
            }
            if (g2) {
                int jn = i2 - k, jp = i2 + k;
                if (jn >= 0)  a2 = fminf(a2, kk + f[jn]);
                if (jp < 160) a2 = fminf(a2, kk + f[jp]);
            }
        }
        res[2 * o]     = a1;
        res[2 * o + 1] = a2;
    }

    __syncthreads();   // all reads of fsh done before overwrite
#pragma unroll
    for (int o = 0; o < 10; o++) fsh[l][s * 10 + o] = res[o];
    __syncthreads();

    // ---- coalesced store ----
    if (MODE == 0) {
        for (int idx = tid; idx < 32 * 160; idx += 512) {
            int ll = idx / 160;
            int j  = idx - ll * 160;
            out[base + idx] = fsh[ll][j];
        }
    } else {
        for (int idx = tid; idx < 32 * 160; idx += 512) {
            int j  = idx >> 5;
            int ll = idx & 31;
            out[base + (long)j * stride + ll] = fsh[ll][j];
        }
    }
}

// ---------------------------------------------------------------------------
// Fused 3x3x3 max + skeleton + multiply. Software-pipelined z-march:
// per slice: STS(regs) -> barrier -> issue next slice LDGs -> compute/emit.
// Block 256 = (x32, y8), xy tile 32x32, z-chunk 10. grid (5,5,64).
// All halo index math hoisted out of the z loop.
// ---------------------------------------------------------------------------
#define SLICE_ELEMS 1156           // 34*34
#define SROW 36                    // padded row
#define SBUF (34 * SROW)

__global__ __launch_bounds__(256) void skel_kernel(const float* __restrict__ img,
                                                   float* __restrict__ out)
{
    __shared__ float sA[2 * SBUF];

    const int tid = threadIdx.x;
    const int tx  = tid & 31;
    const int ty  = tid >> 5;                // 0..7
    const int x0  = blockIdx.x * 32;
    const int y0  = blockIdx.y * 32;
    const int b   = blockIdx.z >> 4;         // 0..3
    const int z0  = (blockIdx.z & 15) * 10;  // 0..150
    const long gbase = (long)b * DHWSZ;
    const float* __restrict__ A = g_A + gbase;

    // ---- hoisted halo-load bookkeeping (loop-invariant) ----
    int  gofs[5];     // gy*WW + gx
    int  sofs[5];     // hy*SROW + hx
    bool inb[5];
#pragma unroll
    for (int r = 0; r < 5; r++) {
        int idx = tid + 256 * r;
        bool it_ok = idx < SLICE_ELEMS;
        int hy = idx / 34;
        int hx = idx - hy * 34;
        int gx = x0 + hx - 1, gy = y0 + hy - 1;
        inb[r]  = it_ok && gx >= 0 && gx < 160 && gy >= 0 && gy < 160;
        gofs[r] = gy * WW + gx;
        sofs[r] = it_ok ? (hy * SROW + hx) : (2 * SBUF - 1) & 0;  // dummy 0 if !it_ok
        if (!it_ok) sofs[r] = -1;
    }

    float v[5];
    // preload slice z0-1 into registers
    {
        const bool zok = (z0 - 1) >= 0;
        const float* __restrict__ S = A + (long)(z0 - 1) * HWSZ;
#pragma unroll
        for (int r = 0; r < 5; r++)
            v[r] = (zok && inb[r]) ? S[gofs[r]] : NEGINF;
    }

    float xa[4], xb[4];       // xy-max at slice zs-2, zs-1
    float ch[4];              // center value at slice zs-1
#pragma unroll
    for (int s_ = 0; s_ < 4; s_++) { xa[s_] = NEGINF; xb[s_] = NEGINF; ch[s_] = 0.0f; }

    // march slices zs = z0-1 .. z0+10
#pragma unroll 1
    for (int it = 0; it < 12; it++) {
        const int zs = z0 - 1 + it;
        float* __restrict__ buf = sA + (it & 1) * SBUF;

        // store current slice registers to shared
#pragma unroll
        for (int r = 0; r < 5; r++)
            if (sofs[r] >= 0) buf[sofs[r]] = v[r];
        __syncthreads();

        // issue LDGs for next slice (overlapped with compute below)
        {
            const int zs2 = zs + 1;
            const bool zok2 = zs2 < 160;
            const float* __restrict__ S2 = A + (long)zs2 * HWSZ;
#pragma unroll
            for (int r = 0; r < 5; r++)
                v[r] = (zok2 && inb[r]) ? S2[gofs[r]] : NEGINF;
        }

        // compute 3x3 xy-max + center for slice zs, emit output for zs-1
#pragma unroll
        for (int s_ = 0; s_ < 4; s_++) {
            const int hy = ty + 8 * s_ + 1;
            const float* row0 = buf + (hy - 1) * SROW + tx;
            const float* row1 = buf + hy * SROW + tx;
            const float* row2 = buf + (hy + 1) * SROW + tx;
            float m0 = fmaxf(fmaxf(row0[0], row0[1]), row0[2]);
            float c  = row1[1];
            float m1 = fmaxf(fmaxf(row1[0], c), row1[2]);
            float m2 = fmaxf(fmaxf(row2[0], row2[1]), row2[2]);
            float xn = fmaxf(fmaxf(m0, m1), m2);

            if (it >= 2) {      // output at zo = zs-1 in [z0, z0+10)
                float m = fmaxf(fmaxf(xa[s_], xb[s_]), xn);
                float cc = ch[s_];
                long gi = gbase + (long)(zs - 1) * HWSZ + (y0 + ty + 8 * s_) * WW + (x0 + tx);
                out[gi] = (cc >= m && cc > 0.0f) ? img[gi] : 0.0f;
            }
            xa[s_] = xb[s_];
            xb[s_] = xn;
            ch[s_] = c;
        }
        // single barrier per slice is safe: any thread's STS to this buf at
        // it+2 occurs after sync(it+1), which follows all compute(it) reads.
    }
}

// ---------------------------------------------------------------------------
extern "C" void kernel_launch(void* const* d_in, const int* in_sizes, int n_in,
                              void* d_out, int out_size)
{
    const float* img = (const float*)d_in[0];
    float* out = (float*)d_out;

    // EDT: x -> y -> z  (g_A holds final d^2)
    edt_pass_kernel<0><<<3200, 512>>>(img);
    edt_pass_kernel<1><<<3200, 512>>>(nullptr);
    edt_pass_kernel<2><<<3200, 512>>>(nullptr);

    // Fused 3x3x3 max + skeleton + multiply (pipelined z-march, 10-slice chunks)
    skel_kernel<<<dim3(5, 5, 64), 256>>>(img, out);
}

// round 9
// speedup vs baseline: 1.4493x; 1.3288x over previous
#include <cuda_runtime.h>

// DMTSkeletonize: exact squared-EDT with adaptive candidate window (bit-exact:
// excluding j with (i-j)^2 >= running-min can't change the min since f >= 0;
// all finite values < 2^24 so kept terms are exactly the reference's), plus a
// software-pipelined z-marching 3x3x3 local-max skeleton on d^2.
//
// Shapes: img [4,1,160,160,160] fp32. B=4, D=H=W=160.

#define WW    160
#define HWSZ  25600      // H*W
#define DHWSZ 4096000    // D*H*W
#define NTOT  16384000   // B*D*H*W
#define FINF  1e12f
#define NEGINF (-3.0e38f)

// Scratch (device globals — no allocation anywhere, per harness rules)
__device__ float g_A[NTOT];
__device__ float g_B[NTOT];

// ---------------------------------------------------------------------------
// EDT 1D pass: out[line][i] = min_j fl(f[line][j] + (i-j)^2)
// MODE 0: x lines (contiguous), input = img binarized -> g_A
// MODE 1: y lines (stride W),   g_A -> g_B
// MODE 2: z lines (stride H*W), g_B -> g_A
// 512 threads, 32 lines/block; thread = (line, segment-of-10); adaptive
// outward scan, two outputs (i, i+5) in flight per thread (ILP=2).
// [Best-measured EDT variant: R6, ~63us/pass]
// ---------------------------------------------------------------------------
template <int MODE>
__global__ __launch_bounds__(512) void edt_pass_kernel(const float* __restrict__ img)
{
    __shared__ float fsh[32][161];  // pad: conflict-free transposed access

    const float* __restrict__ in  = (MODE == 0) ? img : (MODE == 1 ? g_A : g_B);
    float* __restrict__       out = (MODE == 1) ? g_B : g_A;

    const int tid = threadIdx.x;
    const int bid = blockIdx.x;

    long base;
    int stride;
    if (MODE == 0) {
        base = (long)bid * (32 * 160);
        stride = 1;
    } else if (MODE == 1) {
        int p  = bid / 5;            // p = b*160 + z
        int x0 = (bid % 5) * 32;
        base = (long)p * HWSZ + x0;
        stride = WW;
    } else {
        int p  = bid / 5;            // p = b*160 + y
        int x0 = (bid % 5) * 32;
        int b = p / 160, y = p - b * 160;
        base = (long)b * DHWSZ + (long)y * WW + x0;
        stride = HWSZ;
    }

    // ---- load tile into shared (coalesced) ----
    if (MODE == 0) {
        for (int idx = tid; idx < 32 * 160; idx += 512) {
            int l = idx / 160;
            int j = idx - l * 160;
            float v = in[base + idx];
            fsh[l][j] = (v > 0.5f) ? 0.0f : FINF;     // binarize + invert
        }
    } else {
        for (int idx = tid; idx < 32 * 160; idx += 512) {
            int j = idx >> 5;
            int l = idx & 31;
            fsh[l][j] = in[base + (long)j * stride + l];
        }
    }
    __syncthreads();

    // ---- adaptive-window min-plus transform, 2 outputs in flight ----
    const int l = tid >> 4;          // line 0..31
    const int s = tid & 15;          // segment 0..15 (10 outputs each)
    const float* __restrict__ f = fsh[l];

    float res[10];
#pragma unroll 1
    for (int o = 0; o < 5; o++) {
        const int i1 = s * 10 + o;
        const int i2 = i1 + 5;
        float a1 = f[i1];            // j = i term: fl(f+0) = f exactly
        float a2 = f[i2];
#pragma unroll 1
        for (int k = 1; k < 160; k++) {
            const float kk = (float)(k * k);        // exact in fp32
            const bool g1 = kk < a1;
            const bool g2 = kk < a2;
            if (!(g1 | g2)) break;
            if (g1) {
                int jn = i1 - k, jp = i1 + k;
                if (jn >= 0)  a1 = fminf(a1, kk + f[jn]);  // 1 rounding = ref
                if (jp < 160) a1 = fminf(a1, kk + f[jp]);
            }
            if (g2) {
                int jn = i2 - k, jp = i2 + k;
                if (jn >= 0)  a2 = fminf(a2, kk + f[jn]);
                if (jp < 160) a2 = fminf(a2, kk + f[jp]);
            }
        }
        res[o] = a1;
        res[o + 5] = a2;
    }

    __syncthreads();   // all reads of fsh done before overwrite
#pragma unroll
    for (int o = 0; o < 10; o++) fsh[l][s * 10 + o] = res[o];
    __syncthreads();

    // ---- coalesced store ----
    if (MODE == 0) {
        for (int idx = tid; idx < 32 * 160; idx += 512) {
            int ll = idx / 160;
            int j  = idx - ll * 160;
            out[base + idx] = fsh[ll][j];
        }
    } else {
        for (int idx = tid; idx < 32 * 160; idx += 512) {
            int j  = idx >> 5;
            int ll = idx & 31;
            out[base + (long)j * stride + ll] = fsh[ll][j];
        }
    }
}

// ---------------------------------------------------------------------------
// Fused 3x3x3 max + skeleton + multiply. Software-pipelined z-march:
// per slice: STS(regs) -> barrier -> issue next slice LDGs -> compute/emit.
// Block 256 = (x32, y8), xy tile 32x32, z-chunk 10. grid (5,5,64).
// [Best-measured skel variant: R8, ~111us]
// ---------------------------------------------------------------------------
#define SLICE_ELEMS 1156           // 34*34
#define SROW 36                    // padded row
#define SBUF (34 * SROW)

__global__ __launch_bounds__(256) void skel_kernel(const float* __restrict__ img,
                                                   float* __restrict__ out)
{
    __shared__ float sA[2 * SBUF];

    const int tid = threadIdx.x;
    const int tx  = tid & 31;
    const int ty  = tid >> 5;                // 0..7
    const int x0  = blockIdx.x * 32;
    const int y0  = blockIdx.y * 32;
    const int b   = blockIdx.z >> 4;         // 0..3
    const int z0  = (blockIdx.z & 15) * 10;  // 0..150
    const long gbase = (long)b * DHWSZ;
    const float* __restrict__ A = g_A + gbase;

    // ---- hoisted halo-load bookkeeping (loop-invariant) ----
    int  gofs[5];     // gy*WW + gx
    int  sofs[5];     // hy*SROW + hx
    bool inb[5];
#pragma unroll
    for (int r = 0; r < 5; r++) {
        int idx = tid + 256 * r;
        bool it_ok = idx < SLICE_ELEMS;
        int hy = idx / 34;
        int hx = idx - hy * 34;
        int gx = x0 + hx - 1, gy = y0 + hy - 1;
        inb[r]  = it_ok && gx >= 0 && gx < 160 && gy >= 0 && gy < 160;
        gofs[r] = gy * WW + gx;
        sofs[r] = it_ok ? (hy * SROW + hx) : -1;
    }

    float v[5];
    // preload slice z0-1 into registers
    {
        const bool zok = (z0 - 1) >= 0;
        const float* __restrict__ S = A + (long)(z0 - 1) * HWSZ;
#pragma unroll
        for (int r = 0; r < 5; r++)
            v[r] = (zok && inb[r]) ? S[gofs[r]] : NEGINF;
    }

    float xa[4], xb[4];       // xy-max at slice zs-2, zs-1
    float ch[4];              // center value at slice zs-1
#pragma unroll
    for (int s_ = 0; s_ < 4; s_++) { xa[s_] = NEGINF; xb[s_] = NEGINF; ch[s_] = 0.0f; }

    // march slices zs = z0-1 .. z0+10
#pragma unroll 1
    for (int it = 0; it < 12; it++) {
        const int zs = z0 - 1 + it;
        float* __restrict__ buf = sA + (it & 1) * SBUF;

        // store current slice registers to shared
#pragma unroll
        for (int r = 0; r < 5; r++)
            if (sofs[r] >= 0) buf[sofs[r]] = v[r];
        __syncthreads();

        // issue LDGs for next slice (overlapped with compute below)
        {
            const int zs2 = zs + 1;
            const bool zok2 = zs2 < 160;
            const float* __restrict__ S2 = A + (long)zs2 * HWSZ;
#pragma unroll
            for (int r = 0; r < 5; r++)
                v[r] = (zok2 && inb[r]) ? S2[gofs[r]] : NEGINF;
        }

        // compute 3x3 xy-max + center for slice zs, emit output for zs-1
#pragma unroll
        for (int s_ = 0; s_ < 4; s_++) {
            const int hy = ty + 8 * s_ + 1;
            const float* row0 = buf + (hy - 1) * SROW + tx;
            const float* row1 = buf + hy * SROW + tx;
            const float* row2 = buf + (hy + 1) * SROW + tx;
            float m0 = fmaxf(fmaxf(row0[0], row0[1]), row0[2]);
            float c  = row1[1];
            float m1 = fmaxf(fmaxf(row1[0], c), row1[2]);
            float m2 = fmaxf(fmaxf(row2[0], row2[1]), row2[2]);
            float xn = fmaxf(fmaxf(m0, m1), m2);

            if (it >= 2) {      // output at zo = zs-1 in [z0, z0+10)
                float m = fmaxf(fmaxf(xa[s_], xb[s_]), xn);
                float cc = ch[s_];
                long gi = gbase + (long)(zs - 1) * HWSZ + (y0 + ty + 8 * s_) * WW + (x0 + tx);
                out[gi] = (cc >= m && cc > 0.0f) ? img[gi] : 0.0f;
            }
            xa[s_] = xb[s_];
            xb[s_] = xn;
            ch[s_] = c;
        }
        // single barrier per slice is safe: any thread's STS to this buf at
        // it+2 occurs after sync(it+1), which follows all compute(it) reads.
    }
}

// ---------------------------------------------------------------------------
extern "C" void kernel_launch(void* const* d_in, const int* in_sizes, int n_in,
                              void* d_out, int out_size)
{
    const float* img = (const float*)d_in[0];
    float* out = (float*)d_out;

    // EDT: x -> y -> z  (g_A holds final d^2)
    edt_pass_kernel<0><<<3200, 512>>>(img);
    edt_pass_kernel<1><<<3200, 512>>>(nullptr);
    edt_pass_kernel<2><<<3200, 512>>>(nullptr);

    // Fused 3x3x3 max + skeleton + multiply (pipelined z-march, 10-slice chunks)
    skel_kernel<<<dim3(5, 5, 64), 256>>>(img, out);
}

// round 14
// speedup vs baseline: 1.5162x; 1.0462x over previous
#include <cuda_runtime.h>

// DMTSkeletonize: exact squared-EDT + 3x3x3 local-max skeleton on d^2.
// Pass 1 (binary input): nearest-zero via warp shuffle scans (exact).
// Passes 2/3: min-plus transform with STATIC candidate window k^2 < max(f_i)
//   (exact: excluded terms >= k^2 >= f[i] >= final min; all finite arithmetic
//   is integer-valued < 2^24 so every kept term is bit-identical to the ref).
// Shapes: img [4,1,160,160,160] fp32. B=4, D=H=W=160.

#define WW    160
#define HWSZ  25600      // H*W
#define DHWSZ 4096000    // D*H*W
#define NTOT  16384000   // B*D*H*W
#define FINF  1e12f
#define NEGINF (-3.0e38f)

// Scratch (device globals — no allocation anywhere, per harness rules)
__device__ float g_A[NTOT];
__device__ float g_B[NTOT];

// ---------------------------------------------------------------------------
// EDT 1D pass. MODE 0: x lines (img binarized -> g_A), scan-based.
// MODE 1: y lines (stride W), g_A -> g_B.  MODE 2: z lines (stride HW), g_B->g_A.
// 512 threads, 32 lines/block.
// ---------------------------------------------------------------------------
template <int MODE>
__global__ __launch_bounds__(512) void edt_pass_kernel(const float* __restrict__ img)
{
    __shared__ float fsh[32][161];  // pad: conflict-free transposed access

    const float* __restrict__ in  = (MODE == 0) ? img : (MODE == 1 ? g_A : g_B);
    float* __restrict__       out = (MODE == 1) ? g_B : g_A;

    const int tid = threadIdx.x;
    const int bid = blockIdx.x;

    long base;
    int stride;
    if (MODE == 0) {
        base = (long)bid * (32 * 160);
        stride = 1;
    } else if (MODE == 1) {
        int p  = bid / 5;            // p = b*160 + z
        int x0 = (bid % 5) * 32;
        base = (long)p * HWSZ + x0;
        stride = WW;
    } else {
        int p  = bid / 5;            // p = b*160 + y
        int x0 = (bid % 5) * 32;
        int b = p / 160, y = p - b * 160;
        base = (long)b * DHWSZ + (long)y * WW + x0;
        stride = HWSZ;
    }

    // ---- load tile into shared (coalesced) ----
    if (MODE == 0) {
        for (int idx = tid; idx < 32 * 160; idx += 512) {
            int l = idx / 160;
            int j = idx - l * 160;
            float v = in[base + idx];
            fsh[l][j] = (v > 0.5f) ? 0.0f : FINF;     // binarize + invert
        }
    } else {
        for (int idx = tid; idx < 32 * 160; idx += 512) {
            int j = idx >> 5;
            int l = idx & 31;
            fsh[l][j] = in[base + (long)j * stride + l];
        }
    }
    __syncthreads();

    if (MODE == 0) {
        // ---- scan-based nearest-zero: warp = 2 lines, lane = 5-elem chunk ----
        const int warp = tid >> 5;       // 0..15
        const int lane = tid & 31;
#pragma unroll 1
        for (int li = 0; li < 2; li++) {
            const int l = warp * 2 + li;
            float* __restrict__ f = fsh[l];
            const int p0 = 5 * lane;

            float v[5];
#pragma unroll
            for (int c = 0; c < 5; c++) v[c] = f[p0 + c];

            // forward: position of last zero-site (f==0) at or before p
            int lane_last = -1000;
#pragma unroll
            for (int c = 0; c < 5; c++) if (v[c] == 0.0f) lane_last = p0 + c;
            int incl = lane_last;
#pragma unroll
            for (int off = 1; off < 32; off <<= 1) {
                int o = __shfl_up_sync(0xFFFFFFFFu, incl, off);
                if (lane >= off) incl = max(incl, o);
            }
            int excl = __shfl_up_sync(0xFFFFFFFFu, incl, 1);
            if (lane == 0) excl = -1000;

            // backward: position of first zero-site at or after p
            int lane_first = 1000;
#pragma unroll
            for (int c = 4; c >= 0; c--) if (v[c] == 0.0f) lane_first = p0 + c;
            int inclb = lane_first;
#pragma unroll
            for (int off = 1; off < 32; off <<= 1) {
                int o = __shfl_down_sync(0xFFFFFFFFu, inclb, off);
                if (lane + off < 32) inclb = min(inclb, o);
            }
            int exclb = __shfl_down_sync(0xFFFFFFFFu, inclb, 1);
            if (lane == 31) exclb = 1000;

            int nzArr[5];
            int run_nz = exclb;
#pragma unroll
            for (int c = 4; c >= 0; c--) {
                if (v[c] == 0.0f) run_nz = p0 + c;
                nzArr[c] = run_nz;
            }
            int run_lz = excl;
#pragma unroll
            for (int c = 0; c < 5; c++) {
                int p = p0 + c;
                if (v[c] == 0.0f) run_lz = p;
                int d = min(p - run_lz, nzArr[c] - p);
                // writes only this lane's own chunk; no cross-lane readers
                f[p] = (d >= 160) ? FINF : (float)(d * d);
            }
        }
        __syncthreads();
    } else {
        // ---- static-window min-plus transform, 2 chains (i, i+5)/thread ----
        const int l = tid >> 4;          // line 0..31
        const int s = tid & 15;          // segment 0..15 (10 outputs each)
        const float* __restrict__ f = fsh[l];

        float res[10];
#pragma unroll 1
        for (int o = 0; o < 5; o++) {
            const int i1 = s * 10 + o;
            const int i2 = i1 + 5;
            float a1 = f[i1];            // j = i term: exact
            float a2 = f[i2];
            const float Bnd = fmaxf(a1, a2);   // loop-invariant bound
#pragma unroll 1
            for (int k = 1; k < 160; k++) {
                const float kk = (float)(k * k);        // exact in fp32
                if (kk >= Bnd) break;
                int jn1 = i1 - k, jp1 = i1 + k;
                if (jn1 >= 0)  a1 = fminf(a1, kk + f[jn1]);  // single rounding
                if (jp1 < 160) a1 = fminf(a1, kk + f[jp1]);
                int jn2 = i2 - k, jp2 = i2 + k;
                if (jn2 >= 0)  a2 = fminf(a2, kk + f[jn2]);
                if (jp2 < 160) a2 = fminf(a2, kk + f[jp2]);
            }
            res[o] = a1;
            res[o + 5] = a2;
        }

        __syncthreads();   // all reads of fsh done before overwrite
#pragma unroll
        for (int o = 0; o < 10; o++) fsh[l][s * 10 + o] = res[o];
        __syncthreads();
    }

    // ---- coalesced store ----
    if (MODE == 0) {
        for (int idx = tid; idx < 32 * 160; idx += 512) {
            int ll = idx / 160;
            int j  = idx - ll * 160;
            out[base + idx] = fsh[ll][j];
        }
    } else {
        for (int idx = tid; idx < 32 * 160; idx += 512) {
            int j  = idx >> 5;
            int ll = idx & 31;
            out[base + (long)j * stride + ll] = fsh[ll][j];
        }
    }
}

// ---------------------------------------------------------------------------
// Fused 3x3x3 max + skeleton + multiply. Software-pipelined z-march.
// [Best-measured variant, R8/R9: ~87us — unchanged]
// ---------------------------------------------------------------------------
#define SLICE_ELEMS 1156           // 34*34
#define SROW 36                    // padded row
#define SBUF (34 * SROW)

__global__ __launch_bounds__(256) void skel_kernel(const float* __restrict__ img,
                                                   float* __restrict__ out)
{
    __shared__ float sA[2 * SBUF];

    const int tid = threadIdx.x;
    const int tx  = tid & 31;
    const int ty  = tid >> 5;                // 0..7
    const int x0  = blockIdx.x * 32;
    const int y0  = blockIdx.y * 32;
    const int b   = blockIdx.z >> 4;         // 0..3
    const int z0  = (blockIdx.z & 15) * 10;  // 0..150
    const long gbase = (long)b * DHWSZ;
    const float* __restrict__ A = g_A + gbase;

    // ---- hoisted halo-load bookkeeping (loop-invariant) ----
    int  gofs[5];
    int  sofs[5];
    bool inb[5];
#pragma unroll
    for (int r = 0; r < 5; r++) {
        int idx = tid + 256 * r;
        bool it_ok = idx < SLICE_ELEMS;
        int hy = idx / 34;
        int hx = idx - hy * 34;
        int gx = x0 + hx - 1, gy = y0 + hy - 1;
        inb[r]  = it_ok && gx >= 0 && gx < 160 && gy >= 0 && gy < 160;
        gofs[r] = gy * WW + gx;
        sofs[r] = it_ok ? (hy * SROW + hx) : -1;
    }

    float v[5];
    {
        const bool zok = (z0 - 1) >= 0;
        const float* __restrict__ S = A + (long)(z0 - 1) * HWSZ;
#pragma unroll
        for (int r = 0; r < 5; r++)
            v[r] = (zok && inb[r]) ? S[gofs[r]] : NEGINF;
    }

    float xa[4], xb[4];
    float ch[4];
#pragma unroll
    for (int s_ = 0; s_ < 4; s_++) { xa[s_] = NEGINF; xb[s_] = NEGINF; ch[s_] = 0.0f; }

#pragma unroll 1
    for (int it = 0; it < 12; it++) {
        const int zs = z0 - 1 + it;
        float* __restrict__ buf = sA + (it & 1) * SBUF;

#pragma unroll
        for (int r = 0; r < 5; r++)
            if (sofs[r] >= 0) buf[sofs[r]] = v[r];
        __syncthreads();

        {
            const int zs2 = zs + 1;
            const bool zok2 = zs2 < 160;
            const float* __restrict__ S2 = A + (long)zs2 * HWSZ;
#pragma unroll
            for (int r = 0; r < 5; r++)
                v[r] = (zok2 && inb[r]) ? S2[gofs[r]] : NEGINF;
        }

#pragma unroll
        for (int s_ = 0; s_ < 4; s_++) {
            const int hy = ty + 8 * s_ + 1;
            const float* row0 = buf + (hy - 1) * SROW + tx;
            const float* row1 = buf + hy * SROW + tx;
            const float* row2 = buf + (hy + 1) * SROW + tx;
            float m0 = fmaxf(fmaxf(row0[0], row0[1]), row0[2]);
            float c  = row1[1];
            float m1 = fmaxf(fmaxf(row1[0], c), row1[2]);
            float m2 = fmaxf(fmaxf(row2[0], row2[1]), row2[2]);
            float xn = fmaxf(fmaxf(m0, m1), m2);

            if (it >= 2) {
                float m = fmaxf(fmaxf(xa[s_], xb[s_]), xn);
                float cc = ch[s_];
                long gi = gbase + (long)(zs - 1) * HWSZ + (y0 + ty + 8 * s_) * WW + (x0 + tx);
                out[gi] = (cc >= m && cc > 0.0f) ? img[gi] : 0.0f;
            }
            xa[s_] = xb[s_];
            xb[s_] = xn;
            ch[s_] = c;
        }
        // single barrier per slice safe: STS to this buf at it+2 follows
        // sync(it+1), which follows all compute(it) reads.
    }
}

// ---------------------------------------------------------------------------
extern "C" void kernel_launch(void* const* d_in, const int* in_sizes, int n_in,
                              void* d_out, int out_size)
{
    const float* img = (const float*)d_in[0];
    float* out = (float*)d_out;

    // EDT: x -> y -> z  (g_A holds final d^2)
    edt_pass_kernel<0><<<3200, 512>>>(img);
    edt_pass_kernel<1><<<3200, 512>>>(nullptr);
    edt_pass_kernel<2><<<3200, 512>>>(nullptr);

    // Fused 3x3x3 max + skeleton + multiply (pipelined z-march)
    skel_kernel<<<dim3(5, 5, 64), 256>>>(img, out);
}